// round 3
// baseline (speedup 1.0000x reference)
#include <cuda_runtime.h>
#include <cuda_bf16.h>

#define N_NODES 30000
#define E_EDGES 480000

// scratch (device globals: no allocation allowed)
__device__ float g_e[E_EDGES];
__device__ float g_v[E_EDGES * 20];
__device__ float g_q[N_NODES * 20];
__device__ float g_Z[N_NODES];

#define C_SS 0.17677669529663687f   // 1/(4*sqrt2)
#define C_UU 0.14433756729740643f   // 1/sqrt(48)
#define C_SU 0.17677669529663687f   // 1/(4*sqrt2)
#define S0   0.022097086912079608f  // 1/(4*8*sqrt2)
#define S1   0.036084391824351615f  // 1/(sqrt8*4*sqrt3*sqrt2)

typedef unsigned long long ull;

__device__ __forceinline__ void fma2(ull &acc, ull a, ull b) {
    asm("fma.rn.f32x2 %0, %1, %2, %3;" : "=l"(acc) : "l"(a), "l"(b), "l"(acc));
}
__device__ __forceinline__ ull packf2(float lo, float hi) {
    ull r; asm("mov.b64 %0, {%1, %2};" : "=l"(r) : "f"(lo), "f"(hi)); return r;
}
__device__ __forceinline__ float redf2(ull a) {
    float lo, hi; asm("mov.b64 {%0, %1}, %2;" : "=f"(lo), "=f"(hi) : "l"(a)); return lo + hi;
}
__device__ __forceinline__ float silu_f(float x) { return x / (1.f + __expf(-x)); }

// dot of h[64] (packed pairs) with one 64-float shared column (broadcast reads)
__device__ __forceinline__ float dotcol(const float* __restrict__ w, const ull h2[32]) {
    ull acc = 0ull;
    const ulonglong2* wp = (const ulonglong2*)w;
#pragma unroll
    for (int k = 0; k < 16; k++) {
        ulonglong2 wv = wp[k];
        fma2(acc, wv.x, h2[2 * k]);
        fma2(acc, wv.y, h2[2 * k + 1]);
    }
    return redf2(acc);
}

// ---------------------------------------------------------------------------
// Kernel 1: per-node q pre-contraction (+ zero Z and out)
// ---------------------------------------------------------------------------
__global__ void q_kernel(const float* __restrict__ x,
                         const float* __restrict__ Wq0, const float* __restrict__ Wq1,
                         const float* __restrict__ Wd0, const float* __restrict__ Wd1,
                         float* __restrict__ out)
{
    int n = blockIdx.x * blockDim.x + threadIdx.x;
    if (n >= N_NODES) return;
    g_Z[n] = 0.f;
    float* o = out + (size_t)n * 20;
#pragma unroll
    for (int k = 0; k < 20; k++) o[k] = 0.f;

    const float* xr = x + (size_t)n * 40;
    float q0[8];
#pragma unroll
    for (int b = 0; b < 8; b++) {
        float acc = 0.f;
#pragma unroll
        for (int a = 0; a < 16; a++) acc = fmaf(xr[a], __ldg(Wq0 + a * 8 + b), acc);
        q0[b] = acc;
    }
    float q1[12];
#pragma unroll
    for (int b = 0; b < 4; b++)
#pragma unroll
        for (int c = 0; c < 3; c++) {
            float acc = 0.f;
#pragma unroll
            for (int a = 0; a < 8; a++) acc = fmaf(xr[16 + a * 3 + c], __ldg(Wq1 + a * 4 + b), acc);
            q1[b * 3 + c] = acc;
        }
    float* qo = g_q + (size_t)n * 20;
#pragma unroll
    for (int b = 0; b < 8; b++) {
        float acc = 0.f;
#pragma unroll
        for (int a = 0; a < 8; a++) acc = fmaf(q0[a], __ldg(Wd0 + a * 8 + b), acc);
        qo[b] = acc * S0;
    }
#pragma unroll
    for (int b = 0; b < 4; b++)
#pragma unroll
        for (int c = 0; c < 3; c++) {
            float acc = 0.f;
#pragma unroll
            for (int a = 0; a < 4; a++) acc = fmaf(q1[a * 3 + c], __ldg(Wd1 + a * 4 + b), acc);
            qo[8 + b * 3 + c] = acc * S1;
        }
}

// ---------------------------------------------------------------------------
// Kernel 2: fused edge kernel (radial MLPs + tensor products + logits + V)
// SMEM (floats): W2K[18432] W2V[18432] W1K[1024] W1V[1024] OP[64*256]
// ---------------------------------------------------------------------------
#define OFF_W2K 0
#define OFF_W2V 18432
#define OFF_W1K 36864
#define OFF_W1V 37888
#define OFF_OP  38912
#define SMEM_FLOATS 55296

__global__ __launch_bounds__(256, 1)
void edge_kernel(const float* __restrict__ x, const int* __restrict__ ei,
                 const float* __restrict__ eattr, const float* __restrict__ emb,
                 const float* __restrict__ elen,
                 const float* __restrict__ Wk1, const float* __restrict__ Wk2,
                 const float* __restrict__ Wv1, const float* __restrict__ Wv2)
{
    extern __shared__ float smem[];
    const int tid = threadIdx.x;

    // stage weights (transposed, constants folded)
    for (int idx = tid; idx < 1024; idx += 256) {
        int hh = idx >> 4, a = idx & 15;
        smem[OFF_W1K + idx] = Wk1[a * 64 + hh] * 0.25f;
        smem[OFF_W1V + idx] = Wv1[a * 64 + hh] * 0.25f;
    }
    for (int idx = tid; idx < 18432; idx += 256) {
        int col = idx >> 6, hh = idx & 63;
        smem[OFF_W2K + idx] = Wk2[hh * 288 + col] * 0.125f;
        smem[OFF_W2V + idx] = Wv2[hh * 288 + col] * 0.125f;
    }
    __syncthreads();

    for (int base = blockIdx.x * 256; base < E_EDGES; base += gridDim.x * 256) {
        int e = base + tid;
        bool valid = e < E_EDGES;
        int ec = valid ? e : 0;
        int src = ei[ec];
        int dst = ei[E_EDGES + ec];
        float4 ea = *(const float4*)(eattr + (size_t)ec * 4);
        float y0 = ea.x, y1a = ea.y, y1b = ea.z, y1c = ea.w;
        float el = elen[ec];

        // per-thread operands into shared scratch (lane-contiguous layout)
        const float* xr = x + (size_t)src * 40;
        float xs_[16], xu_[24];
#pragma unroll
        for (int a = 0; a < 16; a++) xs_[a] = __ldg(xr + a);
#pragma unroll
        for (int a = 0; a < 24; a++) xu_[a] = __ldg(xr + 16 + a);
        float* op = smem + OFF_OP + tid;
#pragma unroll
        for (int a = 0; a < 16; a++) op[a * 256] = xs_[a] * y0 * C_SS;
#pragma unroll
        for (int a = 0; a < 8; a++)
            op[(16 + a) * 256] = (xu_[a * 3] * y1a + xu_[a * 3 + 1] * y1b + xu_[a * 3 + 2] * y1c) * C_UU;
#pragma unroll
        for (int a = 0; a < 16; a++) op[(24 + a) * 256] = xs_[a] * C_SU;
        float y0q = y0 * 0.25f;
#pragma unroll
        for (int a = 0; a < 24; a++) op[(40 + a) * 256] = xu_[a] * y0q;

        // embedding (packed pairs)
        ull em2[8];
        {
            const float4* ep = (const float4*)(emb + (size_t)ec * 16);
#pragma unroll
            for (int k = 0; k < 4; k++) {
                float4 t = __ldg(ep + k);
                em2[2 * k]     = packf2(t.x, t.y);
                em2[2 * k + 1] = packf2(t.z, t.w);
            }
        }

#pragma unroll 1
        for (int ph = 0; ph < 2; ph++) {
            const float* w1 = smem + (ph ? OFF_W1V : OFF_W1K);
            const float* w2 = smem + (ph ? OFF_W2V : OFF_W2K);

            // first layer -> h[64] packed in registers
            ull h2[32];
#pragma unroll
            for (int p = 0; p < 32; p++) {
                ull a0 = 0ull, a1 = 0ull;
                const ulonglong2* wp0 = (const ulonglong2*)(w1 + (2 * p) * 16);
                const ulonglong2* wp1 = (const ulonglong2*)(w1 + (2 * p + 1) * 16);
#pragma unroll
                for (int k = 0; k < 4; k++) {
                    ulonglong2 wv0 = wp0[k], wv1 = wp1[k];
                    fma2(a0, wv0.x, em2[2 * k]); fma2(a0, wv0.y, em2[2 * k + 1]);
                    fma2(a1, wv1.x, em2[2 * k]); fma2(a1, wv1.y, em2[2 * k + 1]);
                }
                h2[p] = packf2(silu_f(redf2(a0)), silu_f(redf2(a1)));
            }

            float out0[8] = {0, 0, 0, 0, 0, 0, 0, 0};
            float suA[4] = {0, 0, 0, 0};
            float usA[12] = {0, 0, 0, 0, 0, 0, 0, 0, 0, 0, 0, 0};

            // region ss: cols [0,128)
#pragma unroll 1
            for (int a = 0; a < 16; a++) {
                float o = op[a * 256];
                const float* wc = w2 + (a * 8) * 64;
#pragma unroll
                for (int b = 0; b < 8; b++) out0[b] = fmaf(dotcol(wc + b * 64, h2), o, out0[b]);
            }
            // region uu: cols [128,192)
#pragma unroll 1
            for (int a = 0; a < 8; a++) {
                float o = op[(16 + a) * 256];
                const float* wc = w2 + (128 + a * 8) * 64;
#pragma unroll
                for (int b = 0; b < 8; b++) out0[b] = fmaf(dotcol(wc + b * 64, h2), o, out0[b]);
            }
            // region su: cols [192,256)
#pragma unroll 1
            for (int a = 0; a < 16; a++) {
                float o = op[(24 + a) * 256];
                const float* wc = w2 + (192 + a * 4) * 64;
#pragma unroll
                for (int b = 0; b < 4; b++) suA[b] = fmaf(dotcol(wc + b * 64, h2), o, suA[b]);
            }
            // region us: cols [256,288)
#pragma unroll 1
            for (int a = 0; a < 8; a++) {
                float o0 = op[(40 + a * 3) * 256];
                float o1 = op[(41 + a * 3) * 256];
                float o2 = op[(42 + a * 3) * 256];
                const float* wc = w2 + (256 + a * 4) * 64;
#pragma unroll
                for (int b = 0; b < 4; b++) {
                    float wcol = dotcol(wc + b * 64, h2);
                    usA[b * 3]     = fmaf(wcol, o0, usA[b * 3]);
                    usA[b * 3 + 1] = fmaf(wcol, o1, usA[b * 3 + 1]);
                    usA[b * 3 + 2] = fmaf(wcol, o2, usA[b * 3 + 2]);
                }
            }

            if (ph == 0) {
                const float* qd = g_q + (size_t)dst * 20;
                float d = 0.f;
#pragma unroll
                for (int b = 0; b < 8; b++) d = fmaf(out0[b], __ldg(qd + b), d);
#pragma unroll
                for (int b = 0; b < 4; b++) {
                    d = fmaf(fmaf(suA[b], y1a, usA[b * 3]),     __ldg(qd + 8 + b * 3),     d);
                    d = fmaf(fmaf(suA[b], y1b, usA[b * 3 + 1]), __ldg(qd + 8 + b * 3 + 1), d);
                    d = fmaf(fmaf(suA[b], y1c, usA[b * 3 + 2]), __ldg(qd + 8 + b * 3 + 2), d);
                }
                float t = 10.f * (1.f - el * (1.f / 3.15f));
                float cut = (t > 0.f) ? expf(-1.f / fmaxf(t, 1e-6f)) : 0.f;
                float eat = cut * expf(d);
                if (valid) {
                    g_e[e] = eat;
                    atomicAdd(&g_Z[dst], eat);
                }
            } else {
                if (valid) {
                    float* vp = g_v + (size_t)e * 20;
#pragma unroll
                    for (int b = 0; b < 8; b++) vp[b] = out0[b];
#pragma unroll
                    for (int b = 0; b < 4; b++) {
                        vp[8 + b * 3]     = fmaf(suA[b], y1a, usA[b * 3]);
                        vp[8 + b * 3 + 1] = fmaf(suA[b], y1b, usA[b * 3 + 1]);
                        vp[8 + b * 3 + 2] = fmaf(suA[b], y1c, usA[b * 3 + 2]);
                    }
                }
            }
        }
    }
}

// ---------------------------------------------------------------------------
// Kernel 3: normalize + scatter
// ---------------------------------------------------------------------------
__global__ void scatter_kernel(const int* __restrict__ ei, float* __restrict__ out)
{
    int e = blockIdx.x * blockDim.x + threadIdx.x;
    if (e >= E_EDGES) return;
    int dst = ei[E_EDGES + e];
    float w = sqrtf(fmaxf(g_e[e] / g_Z[dst], 0.f));
    const float* vp = g_v + (size_t)e * 20;
    float* op = out + (size_t)dst * 20;
#pragma unroll
    for (int k = 0; k < 20; k++) atomicAdd(op + k, w * __ldg(vp + k));
}

// ---------------------------------------------------------------------------
extern "C" void kernel_launch(void* const* d_in, const int* in_sizes, int n_in,
                              void* d_out, int out_size)
{
    const float* x    = (const float*)d_in[0];
    const int*   ei   = (const int*)d_in[1];
    const float* eatt = (const float*)d_in[2];
    const float* emb  = (const float*)d_in[3];
    const float* elen = (const float*)d_in[4];
    const float* Wq0  = (const float*)d_in[5];
    const float* Wq1  = (const float*)d_in[6];
    const float* Wk1  = (const float*)d_in[7];
    const float* Wk2  = (const float*)d_in[8];
    const float* Wv1  = (const float*)d_in[9];
    const float* Wv2  = (const float*)d_in[10];
    const float* Wd0  = (const float*)d_in[11];
    const float* Wd1  = (const float*)d_in[12];
    float* out = (float*)d_out;

    cudaFuncSetAttribute(edge_kernel, cudaFuncAttributeMaxDynamicSharedMemorySize,
                         SMEM_FLOATS * sizeof(float));
    int dev = 0, nsm = 148;
    cudaGetDevice(&dev);
    cudaDeviceGetAttribute(&nsm, cudaDevAttrMultiProcessorCount, dev);

    q_kernel<<<(N_NODES + 255) / 256, 256>>>(x, Wq0, Wq1, Wd0, Wd1, out);
    edge_kernel<<<nsm, 256, SMEM_FLOATS * sizeof(float)>>>(x, ei, eatt, emb, elen,
                                                           Wk1, Wk2, Wv1, Wv2);
    scatter_kernel<<<(E_EDGES + 255) / 256, 256>>>(ei, out);
    (void)in_sizes; (void)n_in; (void)out_size;
}

// round 5
// speedup vs baseline: 1.4805x; 1.4805x over previous
#include <cuda_runtime.h>
#include <cuda_bf16.h>

#define N_NODES 30000
#define E_EDGES 480000
#define NTILES  3750            // E / 128

// ---------------- device scratch (no allocation allowed) ----------------
__device__ float g_e[E_EDGES];
__device__ float g_v[E_EDGES * 20];
__device__ float g_q[N_NODES * 20];
__device__ float g_Z[N_NODES];

#define C_SS 0.17677669529663687f   // 1/(4*sqrt2)
#define C_UU 0.14433756729740643f   // 1/sqrt(48)
#define C_SU 0.17677669529663687f
#define C_US 0.25f                  // 1/(sqrt8*sqrt2)
#define S0   0.022097086912079608f  // 0.25/(8*sqrt2)
#define S1   0.036084391824351615f  // 1/(sqrt8*4*sqrt3*sqrt2)

typedef unsigned long long ull;
typedef unsigned int u32;
typedef unsigned short u16;

// ---------------- SMEM layout (bytes) ----------------
#define W2STRIDE 132            // 66 bf16 per row (64 used)
#define HSTRIDE  136            // 68 bf16 per row (64 used), 8B-aligned rows
#define OFF_KHI 0
#define OFF_KLO 38016
#define OFF_VHI 76032
#define OFF_VLO 114048
#define OFF_HHI 152064
#define OFF_HLO 169472
#define OFF_W1K 186880
#define OFF_W1V 190976
#define OFF_OPS 195072          // 68 rows x 128 cols x f32 = 34816
#define SMEM_BYTES 229888

// ---------------- helpers ----------------
__device__ __forceinline__ u32 smem_u32(const void* p) {
    u32 a; asm("{ .reg .u64 t; cvta.to.shared.u64 t, %1; cvt.u32.u64 %0, t; }" : "=r"(a) : "l"(p));
    return a;
}
__device__ __forceinline__ u32 lds32(u32 a) {
    u32 v; asm volatile("ld.shared.b32 %0, [%1];" : "=r"(v) : "r"(a)); return v;
}
__device__ __forceinline__ float ldsf(u32 a) {
    float v; asm volatile("ld.shared.f32 %0, [%1];" : "=f"(v) : "r"(a)); return v;
}
__device__ __forceinline__ void stsf(u32 a, float v) {
    asm volatile("st.shared.f32 [%0], %1;" :: "r"(a), "f"(v) : "memory");
}
__device__ __forceinline__ void sts64(u32 a, u32 v0, u32 v1) {
    asm volatile("st.shared.v2.b32 [%0], {%1,%2};" :: "r"(a), "r"(v0), "r"(v1) : "memory");
}
__device__ __forceinline__ void fma2(ull &acc, ull a, ull b) {
    asm("fma.rn.f32x2 %0, %1, %2, %3;" : "=l"(acc) : "l"(a), "l"(b), "l"(acc));
}
__device__ __forceinline__ ull packf2(float lo, float hi) {
    ull r; asm("mov.b64 %0, {%1, %2};" : "=l"(r) : "f"(lo), "f"(hi)); return r;
}
__device__ __forceinline__ float redf2(ull a) {
    float lo, hi; asm("mov.b64 {%0, %1}, %2;" : "=f"(lo), "=f"(hi) : "l"(a)); return lo + hi;
}
__device__ __forceinline__ float silu_f(float x) { return x / (1.f + __expf(-x)); }

__device__ __forceinline__ void bsplit(float x, u16 &h, u16 &l) {
    __nv_bfloat16 bh = __float2bfloat16(x);
    h = __bfloat16_as_ushort(bh);
    l = __bfloat16_as_ushort(__float2bfloat16(x - __bfloat162float(bh)));
}

__device__ __forceinline__ float dot16(const float* w, const ull em2[8]) {
    ull a0 = 0ull, a1 = 0ull;
    const ulonglong2* wp = (const ulonglong2*)w;
#pragma unroll
    for (int k = 0; k < 4; k++) {
        ulonglong2 wv = wp[k];
        fma2(a0, wv.x, em2[2 * k]);
        fma2(a1, wv.y, em2[2 * k + 1]);
    }
    return redf2(a0) + redf2(a1);
}

__device__ __forceinline__ void mma16816(float c[4], const u32* a, u32 b0, u32 b1) {
    asm("mma.sync.aligned.m16n8k16.row.col.f32.bf16.bf16.f32 "
        "{%0,%1,%2,%3}, {%4,%5,%6,%7}, {%8,%9}, {%0,%1,%2,%3};"
        : "+f"(c[0]), "+f"(c[1]), "+f"(c[2]), "+f"(c[3])
        : "r"(a[0]), "r"(a[1]), "r"(a[2]), "r"(a[3]), "r"(b0), "r"(b1));
}

// MMA for one n-chunk pair (cols [ch*8, ch*8+16)), 3 bf16-split passes, K=64.
__device__ __forceinline__ void mma_pair(u32 bH, u32 bL, int ch, int j, int qr,
                                         const u32* ah, const u32* al,
                                         float A0[4], float B0[4], float A1[4], float B1[4])
{
    const u32 nb0 = (u32)((ch * 8 + qr) * W2STRIDE + 4 * j);
    const u32 nb1 = nb0 + 8 * W2STRIDE;
#pragma unroll
    for (int pass = 0; pass < 3; pass++) {
        const u32* af = (pass == 2) ? al : ah;
        const u32 bb = (pass == 1) ? bL : bH;
#pragma unroll
        for (int kt = 0; kt < 4; kt++) {
            u32 p0a = bb + nb0 + kt * 32;
            u32 b00 = lds32(p0a), b01 = lds32(p0a + 16);
            u32 p1a = bb + nb1 + kt * 32;
            u32 b10 = lds32(p1a), b11 = lds32(p1a + 16);
            mma16816(A0, af + (0 * 4 + kt) * 4, b00, b01);
            mma16816(B0, af + (1 * 4 + kt) * 4, b00, b01);
            mma16816(A1, af + (0 * 4 + kt) * 4, b10, b11);
            mma16816(B1, af + (1 * 4 + kt) * 4, b10, b11);
        }
    }
}

// epilogue: accumulate P * op[arow][row] into per-(row,colpair) partials
__device__ __forceinline__ void epi2(u32 ops4, int arow, const int rowv[4],
                                     const float A[4], const float B[4], float p[4][2])
{
#pragma unroll
    for (int rr = 0; rr < 4; rr++) {
        float c0 = (rr < 2) ? A[(rr & 1) * 2]     : B[(rr & 1) * 2];
        float c1 = (rr < 2) ? A[(rr & 1) * 2 + 1] : B[(rr & 1) * 2 + 1];
        float o = ldsf(ops4 + (u32)((arow * 128 + rowv[rr]) * 4));
        p[rr][0] = fmaf(c0, o, p[rr][0]);
        p[rr][1] = fmaf(c1, o, p[rr][1]);
    }
}

__device__ __forceinline__ void epi_us(u32 ops4, int abase, const int rowv[4],
                                       const float A[4], const float B[4], float pus[4][6])
{
#pragma unroll
    for (int rr = 0; rr < 4; rr++) {
        float c0 = (rr < 2) ? A[(rr & 1) * 2]     : B[(rr & 1) * 2];
        float c1 = (rr < 2) ? A[(rr & 1) * 2 + 1] : B[(rr & 1) * 2 + 1];
        u32 base = ops4 + (u32)((abase * 128 + rowv[rr]) * 4);
        float o0 = ldsf(base), o1 = ldsf(base + 512), o2 = ldsf(base + 1024);
        pus[rr][0] = fmaf(c0, o0, pus[rr][0]);
        pus[rr][1] = fmaf(c0, o1, pus[rr][1]);
        pus[rr][2] = fmaf(c0, o2, pus[rr][2]);
        pus[rr][3] = fmaf(c1, o0, pus[rr][3]);
        pus[rr][4] = fmaf(c1, o1, pus[rr][4]);
        pus[rr][5] = fmaf(c1, o2, pus[rr][5]);
    }
}

// ---------------------------------------------------------------------------
// Kernel 1: per-node q pre-contraction (+ zero Z and out)
// ---------------------------------------------------------------------------
__global__ void q_kernel(const float* __restrict__ x,
                         const float* __restrict__ Wq0, const float* __restrict__ Wq1,
                         const float* __restrict__ Wd0, const float* __restrict__ Wd1,
                         float* __restrict__ out)
{
    int n = blockIdx.x * blockDim.x + threadIdx.x;
    if (n >= N_NODES) return;
    g_Z[n] = 0.f;
    float* o = out + (size_t)n * 20;
#pragma unroll
    for (int k = 0; k < 20; k++) o[k] = 0.f;

    const float* xr = x + (size_t)n * 40;
    float q0[8];
#pragma unroll
    for (int b = 0; b < 8; b++) {
        float acc = 0.f;
#pragma unroll
        for (int a = 0; a < 16; a++) acc = fmaf(xr[a], __ldg(Wq0 + a * 8 + b), acc);
        q0[b] = acc;
    }
    float q1[12];
#pragma unroll
    for (int b = 0; b < 4; b++)
#pragma unroll
        for (int c = 0; c < 3; c++) {
            float acc = 0.f;
#pragma unroll
            for (int a = 0; a < 8; a++) acc = fmaf(xr[16 + a * 3 + c], __ldg(Wq1 + a * 4 + b), acc);
            q1[b * 3 + c] = acc;
        }
    float* qo = g_q + (size_t)n * 20;
#pragma unroll
    for (int b = 0; b < 8; b++) {
        float acc = 0.f;
#pragma unroll
        for (int a = 0; a < 8; a++) acc = fmaf(q0[a], __ldg(Wd0 + a * 8 + b), acc);
        qo[b] = acc * S0;
    }
#pragma unroll
    for (int b = 0; b < 4; b++)
#pragma unroll
        for (int c = 0; c < 3; c++) {
            float acc = 0.f;
#pragma unroll
            for (int a = 0; a < 4; a++) acc = fmaf(q1[a * 3 + c], __ldg(Wd1 + a * 4 + b), acc);
            qo[8 + b * 3 + c] = acc * S1;
        }
}

// ---------------------------------------------------------------------------
// Kernel 2: tensor-core (mma.sync) edge kernel
// ---------------------------------------------------------------------------
__global__ __launch_bounds__(128, 1)
void edge_kernel(const float* __restrict__ x, const int* __restrict__ ei,
                 const float* __restrict__ eattr, const float* __restrict__ emb,
                 const float* __restrict__ elen,
                 const float* __restrict__ Wk1, const float* __restrict__ Wk2,
                 const float* __restrict__ Wv1, const float* __restrict__ Wv2)
{
    extern __shared__ char smem[];
    const u32 sb = smem_u32(smem);
    const int tid = threadIdx.x;
    const int lane = tid & 31;
    const int j = lane & 3;
    const int qr = lane >> 2;
    const int wbase = (tid >> 5) << 5;

    // ---- stage W1 (transposed, *0.25) ----
    float* w1k = (float*)(smem + OFF_W1K);
    float* w1v = (float*)(smem + OFF_W1V);
    for (int idx = tid; idx < 1024; idx += 128) {
        int hh = idx >> 4, a = idx & 15;
        w1k[idx] = Wk1[a * 64 + hh] * 0.25f;
        w1v[idx] = Wv1[a * 64 + hh] * 0.25f;
    }
    // ---- stage W2 (transposed [n][k], *0.125, bf16 hi/lo) ----
    for (int idx = tid; idx < 64 * 288; idx += 128) {
        int k = idx / 288, n = idx % 288;
        u32 off = (u32)(n * W2STRIDE + k * 2);
        u16 hb, lb;
        bsplit(Wk2[idx] * 0.125f, hb, lb);
        *(u16*)(smem + OFF_KHI + off) = hb;
        *(u16*)(smem + OFF_KLO + off) = lb;
        bsplit(Wv2[idx] * 0.125f, hb, lb);
        *(u16*)(smem + OFF_VHI + off) = hb;
        *(u16*)(smem + OFF_VLO + off) = lb;
    }

    const u32 ops4 = sb + OFF_OPS;
    int rowv[4];
#pragma unroll
    for (int rr = 0; rr < 4; rr++) rowv[rr] = wbase + (rr >> 1) * 16 + (rr & 1) * 8 + qr;

    for (int tile = blockIdx.x; tile < NTILES; tile += gridDim.x) {
        const int tbase = tile * 128;
        const int e = tbase + tid;
        __syncthreads();    // previous tile's readers done (also covers W2 staging on tile 0)

        // ---- per-edge operand table (own edge -> column tid) ----
        ull em2[8];
        {
            const int src = ei[e];
            const float4 ea = *(const float4*)(eattr + (size_t)e * 4);
            const float y0 = ea.x, y1a = ea.y, y1b = ea.z, y1c = ea.w;
            const float* xr = x + (size_t)src * 40;
            float xs_[16], xu_[24];
#pragma unroll
            for (int a = 0; a < 16; a++) xs_[a] = __ldg(xr + a);
#pragma unroll
            for (int a = 0; a < 24; a++) xu_[a] = __ldg(xr + 16 + a);
#pragma unroll
            for (int a = 0; a < 16; a++) stsf(ops4 + (u32)((a * 128 + tid) * 4), xs_[a] * y0 * C_SS);
#pragma unroll
            for (int a = 0; a < 8; a++)
                stsf(ops4 + (u32)(((16 + a) * 128 + tid) * 4),
                     (xu_[a * 3] * y1a + xu_[a * 3 + 1] * y1b + xu_[a * 3 + 2] * y1c) * C_UU);
#pragma unroll
            for (int a = 0; a < 16; a++) stsf(ops4 + (u32)(((24 + a) * 128 + tid) * 4), xs_[a] * C_SU);
            const float y0q = y0 * C_US;
#pragma unroll
            for (int a = 0; a < 24; a++) stsf(ops4 + (u32)(((40 + a) * 128 + tid) * 4), xu_[a] * y0q);
            stsf(ops4 + (u32)((64 * 128 + tid) * 4), y1a);
            stsf(ops4 + (u32)((65 * 128 + tid) * 4), y1b);
            stsf(ops4 + (u32)((66 * 128 + tid) * 4), y1c);
            stsf(ops4 + (u32)((67 * 128 + tid) * 4), elen[e]);

            const float4* ep = (const float4*)(emb + (size_t)e * 16);
#pragma unroll
            for (int k = 0; k < 4; k++) {
                float4 t = __ldg(ep + k);
                em2[2 * k]     = packf2(t.x, t.y);
                em2[2 * k + 1] = packf2(t.z, t.w);
            }
        }

#pragma unroll 1
        for (int ph = 0; ph < 2; ph++) {
            const float* w1 = ph ? w1v : w1k;

            // ---- first layer: h[64] for own edge -> H smem (bf16 hi/lo) ----
#pragma unroll 1
            for (int g = 0; g < 8; g++) {
                float hv[8];
#pragma unroll
                for (int t = 0; t < 8; t++) hv[t] = silu_f(dot16(w1 + (g * 8 + t) * 16, em2));
                u32 hw[4], lw[4];
#pragma unroll
                for (int t = 0; t < 4; t++) {
                    u16 h0, l0, h1, l1;
                    bsplit(hv[2 * t], h0, l0);
                    bsplit(hv[2 * t + 1], h1, l1);
                    hw[t] = ((u32)h1 << 16) | h0;
                    lw[t] = ((u32)l1 << 16) | l0;
                }
                u32 so = (u32)(tid * HSTRIDE + g * 16);
                sts64(sb + OFF_HHI + so,     hw[0], hw[1]);
                sts64(sb + OFF_HHI + so + 8, hw[2], hw[3]);
                sts64(sb + OFF_HLO + so,     lw[0], lw[1]);
                sts64(sb + OFF_HLO + so + 8, lw[2], lw[3]);
            }
            __syncthreads();

            // ---- load A fragments (this warp's 32 rows, K=64, hi+lo) ----
            u32 ah[32], al[32];
#pragma unroll
            for (int mt = 0; mt < 2; mt++)
#pragma unroll
                for (int kt = 0; kt < 4; kt++) {
                    u32 rb = (u32)((wbase + mt * 16 + qr) * HSTRIDE + 4 * j + kt * 32);
                    int ix = (mt * 4 + kt) * 4;
                    ah[ix + 0] = lds32(sb + OFF_HHI + rb);
                    ah[ix + 1] = lds32(sb + OFF_HHI + rb + 8 * HSTRIDE);
                    ah[ix + 2] = lds32(sb + OFF_HHI + rb + 16);
                    ah[ix + 3] = lds32(sb + OFF_HHI + rb + 8 * HSTRIDE + 16);
                    al[ix + 0] = lds32(sb + OFF_HLO + rb);
                    al[ix + 1] = lds32(sb + OFF_HLO + rb + 8 * HSTRIDE);
                    al[ix + 2] = lds32(sb + OFF_HLO + rb + 16);
                    al[ix + 3] = lds32(sb + OFF_HLO + rb + 8 * HSTRIDE + 16);
                }
            __syncthreads();   // H free for next phase after this

            const u32 bH = sb + (ph ? OFF_VHI : OFF_KHI);
            const u32 bL = sb + (ph ? OFF_VLO : OFF_KLO);

            float p0[4][2]  = {{0,0},{0,0},{0,0},{0,0}};
            float psu[4][2] = {{0,0},{0,0},{0,0},{0,0}};
            float pus[4][6] = {{0,0,0,0,0,0},{0,0,0,0,0,0},{0,0,0,0,0,0},{0,0,0,0,0,0}};

            // ss region: chunks 0..15 (a = ch)
#pragma unroll 2
            for (int ch = 0; ch < 16; ch += 2) {
                float A0[4] = {0,0,0,0}, B0[4] = {0,0,0,0}, A1[4] = {0,0,0,0}, B1[4] = {0,0,0,0};
                mma_pair(bH, bL, ch, j, qr, ah, al, A0, B0, A1, B1);
                epi2(ops4, ch,     rowv, A0, B0, p0);
                epi2(ops4, ch + 1, rowv, A1, B1, p0);
            }
            // uu region: chunks 16..23 (ops row = ch)
#pragma unroll 2
            for (int ch = 16; ch < 24; ch += 2) {
                float A0[4] = {0,0,0,0}, B0[4] = {0,0,0,0}, A1[4] = {0,0,0,0}, B1[4] = {0,0,0,0};
                mma_pair(bH, bL, ch, j, qr, ah, al, A0, B0, A1, B1);
                epi2(ops4, ch,     rowv, A0, B0, p0);
                epi2(ops4, ch + 1, rowv, A1, B1, p0);
            }
            // su region: chunks 24..31 (2 a per chunk, thread takes j>>1 half)
#pragma unroll 2
            for (int ch = 24; ch < 32; ch += 2) {
                float A0[4] = {0,0,0,0}, B0[4] = {0,0,0,0}, A1[4] = {0,0,0,0}, B1[4] = {0,0,0,0};
                mma_pair(bH, bL, ch, j, qr, ah, al, A0, B0, A1, B1);
                epi2(ops4, 2 * ch - 24 + (j >> 1),     rowv, A0, B0, psu);
                epi2(ops4, 2 * (ch + 1) - 24 + (j >> 1), rowv, A1, B1, psu);
            }
            // us region: chunks 32..35
#pragma unroll 2
            for (int ch = 32; ch < 36; ch += 2) {
                float A0[4] = {0,0,0,0}, B0[4] = {0,0,0,0}, A1[4] = {0,0,0,0}, B1[4] = {0,0,0,0};
                mma_pair(bH, bL, ch, j, qr, ah, al, A0, B0, A1, B1);
                epi_us(ops4, 6 * ch - 152 + 3 * (j >> 1),       rowv, A0, B0, pus);
                epi_us(ops4, 6 * (ch + 1) - 152 + 3 * (j >> 1), rowv, A1, B1, pus);
            }

            if (ph == 0) {
                // ---- logit finalize ----
#pragma unroll
                for (int rr = 0; rr < 4; rr++) {
                    const int row = rowv[rr];
                    const int edge = tbase + row;
                    const int dst = __ldg(ei + E_EDGES + edge);
                    const float* qd = g_q + (size_t)dst * 20;
                    const float y1a = ldsf(ops4 + (u32)((64 * 128 + row) * 4));
                    const float y1b = ldsf(ops4 + (u32)((65 * 128 + row) * 4));
                    const float y1c = ldsf(ops4 + (u32)((66 * 128 + row) * 4));
                    const int b0 = (2 * j) & 3, b1 = (2 * j + 1) & 3;
                    const float qa0 = __ldg(qd + 8 + 3 * b0), qa1 = __ldg(qd + 8 + 3 * b0 + 1), qa2 = __ldg(qd + 8 + 3 * b0 + 2);
                    const float qb0 = __ldg(qd + 8 + 3 * b1), qb1 = __ldg(qd + 8 + 3 * b1 + 1), qb2 = __ldg(qd + 8 + 3 * b1 + 2);
                    float dp = p0[rr][0] * __ldg(qd + 2 * j) + p0[rr][1] * __ldg(qd + 2 * j + 1);
                    dp += psu[rr][0] * (y1a * qa0 + y1b * qa1 + y1c * qa2);
                    dp += psu[rr][1] * (y1a * qb0 + y1b * qb1 + y1c * qb2);
                    dp += pus[rr][0] * qa0 + pus[rr][1] * qa1 + pus[rr][2] * qa2;
                    dp += pus[rr][3] * qb0 + pus[rr][4] * qb1 + pus[rr][5] * qb2;
                    dp += __shfl_xor_sync(0xffffffffu, dp, 1);
                    dp += __shfl_xor_sync(0xffffffffu, dp, 2);
                    if (j == 0) {
                        const float el = ldsf(ops4 + (u32)((67 * 128 + row) * 4));
                        const float t = 10.f * (1.f - el * (1.f / 3.15f));
                        const float cut = (t > 0.f) ? expf(-1.f / fmaxf(t, 1e-6f)) : 0.f;
                        const float eat = cut * expf(dp);
                        g_e[edge] = eat;
                        atomicAdd(&g_Z[dst], eat);
                    }
                }
            } else {
                // ---- value finalize ----
#pragma unroll
                for (int rr = 0; rr < 4; rr++) {
                    const int row = rowv[rr];
                    const int edge = tbase + row;
                    float* vp = g_v + (size_t)edge * 20;
                    vp[2 * j]     = p0[rr][0];
                    vp[2 * j + 1] = p0[rr][1];
                    const float s0v = psu[rr][0] + __shfl_xor_sync(0xffffffffu, psu[rr][0], 2);
                    const float s1v = psu[rr][1] + __shfl_xor_sync(0xffffffffu, psu[rr][1], 2);
                    float ux[6];
#pragma unroll
                    for (int c = 0; c < 6; c++)
                        ux[c] = pus[rr][c] + __shfl_xor_sync(0xffffffffu, pus[rr][c], 2);
                    if (j < 2) {
                        const float y1a = ldsf(ops4 + (u32)((64 * 128 + row) * 4));
                        const float y1b = ldsf(ops4 + (u32)((65 * 128 + row) * 4));
                        const float y1c = ldsf(ops4 + (u32)((66 * 128 + row) * 4));
                        const int b0 = 2 * j, b1 = 2 * j + 1;
                        vp[8 + 3 * b0]     = fmaf(s0v, y1a, ux[0]);
                        vp[8 + 3 * b0 + 1] = fmaf(s0v, y1b, ux[1]);
                        vp[8 + 3 * b0 + 2] = fmaf(s0v, y1c, ux[2]);
                        vp[8 + 3 * b1]     = fmaf(s1v, y1a, ux[3]);
                        vp[8 + 3 * b1 + 1] = fmaf(s1v, y1b, ux[4]);
                        vp[8 + 3 * b1 + 2] = fmaf(s1v, y1c, ux[5]);
                    }
                }
            }
        }
    }
}

// ---------------------------------------------------------------------------
// Kernel 3: normalize + scatter
// ---------------------------------------------------------------------------
__global__ void scatter_kernel(const int* __restrict__ ei, float* __restrict__ out)
{
    int e = blockIdx.x * blockDim.x + threadIdx.x;
    if (e >= E_EDGES) return;
    int dst = ei[E_EDGES + e];
    float w = sqrtf(fmaxf(g_e[e] / g_Z[dst], 0.f));
    const float* vp = g_v + (size_t)e * 20;
    float* op = out + (size_t)dst * 20;
#pragma unroll
    for (int k = 0; k < 20; k++) atomicAdd(op + k, w * __ldg(vp + k));
}

// ---------------------------------------------------------------------------
extern "C" void kernel_launch(void* const* d_in, const int* in_sizes, int n_in,
                              void* d_out, int out_size)
{
    const float* x    = (const float*)d_in[0];
    const int*   ei   = (const int*)d_in[1];
    const float* eatt = (const float*)d_in[2];
    const float* emb  = (const float*)d_in[3];
    const float* elen = (const float*)d_in[4];
    const float* Wq0  = (const float*)d_in[5];
    const float* Wq1  = (const float*)d_in[6];
    const float* Wk1  = (const float*)d_in[7];
    const float* Wk2  = (const float*)d_in[8];
    const float* Wv1  = (const float*)d_in[9];
    const float* Wv2  = (const float*)d_in[10];
    const float* Wd0  = (const float*)d_in[11];
    const float* Wd1  = (const float*)d_in[12];
    float* out = (float*)d_out;

    cudaFuncSetAttribute(edge_kernel, cudaFuncAttributeMaxDynamicSharedMemorySize, SMEM_BYTES);
    int dev = 0, nsm = 148;
    cudaGetDevice(&dev);
    cudaDeviceGetAttribute(&nsm, cudaDevAttrMultiProcessorCount, dev);

    q_kernel<<<(N_NODES + 255) / 256, 256>>>(x, Wq0, Wq1, Wd0, Wd1, out);
    edge_kernel<<<nsm, 128, SMEM_BYTES>>>(x, ei, eatt, emb, elen, Wk1, Wk2, Wv1, Wv2);
    scatter_kernel<<<(E_EDGES + 255) / 256, 256>>>(ei, out);
    (void)in_sizes; (void)n_in; (void)out_size;
}

// round 6
// speedup vs baseline: 1.9630x; 1.3259x over previous
#include <cuda_runtime.h>
#include <cuda_bf16.h>

#define N_NODES 30000
#define E_EDGES 480000
#define NTILES  3750            // E / 128

// ---------------- device scratch (no allocation allowed) ----------------
__device__ float g_e[E_EDGES];
__device__ float g_v[E_EDGES * 20];
__device__ float g_q[N_NODES * 20];
__device__ float g_Z[N_NODES];

#define C_SS 0.17677669529663687f   // 1/(4*sqrt2)
#define C_UU 0.14433756729740643f   // 1/sqrt(48)
#define C_SU 0.17677669529663687f
#define C_US 0.25f                  // 1/(sqrt8*sqrt2)
#define S0   0.022097086912079608f
#define S1   0.036084391824351615f

typedef unsigned long long ull;
typedef unsigned int u32;
typedef unsigned short u16;

// ---------------- SMEM layout (bytes) ----------------
// W2 hi buffers: stride 136 (34 words -> ~2-way max LDS conflicts)
// W2 lo buffers: stride 132 (fits budget; lo pass is 1/3 of loads)
// H buffers: stride 132, per-group hi/lo
#define OFF_KHI 0
#define OFF_VHI 39168
#define OFF_KLO 78336
#define OFF_VLO 116352
#define OFF_H0H 154368
#define OFF_H0L 171264
#define OFF_H1H 188160
#define OFF_H1L 205056
#define OFF_W1K 221952
#define OFF_W1V 226048
#define SMEM_BYTES 230144

// ---------------- helpers ----------------
__device__ __forceinline__ u32 smem_u32(const void* p) {
    u32 a; asm("{ .reg .u64 t; cvta.to.shared.u64 t, %1; cvt.u32.u64 %0, t; }" : "=r"(a) : "l"(p));
    return a;
}
__device__ __forceinline__ u32 lds32(u32 a) {
    u32 v; asm volatile("ld.shared.b32 %0, [%1];" : "=r"(v) : "r"(a)); return v;
}
__device__ __forceinline__ void sts32(u32 a, u32 v) {
    asm volatile("st.shared.b32 [%0], %1;" :: "r"(a), "r"(v) : "memory");
}
__device__ __forceinline__ void fma2(ull &acc, ull a, ull b) {
    asm("fma.rn.f32x2 %0, %1, %2, %3;" : "=l"(acc) : "l"(a), "l"(b), "l"(acc));
}
__device__ __forceinline__ ull packf2(float lo, float hi) {
    ull r; asm("mov.b64 %0, {%1, %2};" : "=l"(r) : "f"(lo), "f"(hi)); return r;
}
__device__ __forceinline__ float redf2(ull a) {
    float lo, hi; asm("mov.b64 {%0, %1}, %2;" : "=f"(lo), "=f"(hi) : "l"(a)); return lo + hi;
}
__device__ __forceinline__ float silu_f(float x) { return x / (1.f + __expf(-x)); }

__device__ __forceinline__ void bsplit(float x, u16 &h, u16 &l) {
    __nv_bfloat16 bh = __float2bfloat16(x);
    h = __bfloat16_as_ushort(bh);
    l = __bfloat16_as_ushort(__float2bfloat16(x - __bfloat162float(bh)));
}

__device__ __forceinline__ float dot16(const float* w, const ull em2[8]) {
    ull a0 = 0ull, a1 = 0ull;
    const ulonglong2* wp = (const ulonglong2*)w;
#pragma unroll
    for (int k = 0; k < 4; k++) {
        ulonglong2 wv = wp[k];
        fma2(a0, wv.x, em2[2 * k]);
        fma2(a1, wv.y, em2[2 * k + 1]);
    }
    return redf2(a0) + redf2(a1);
}

__device__ __forceinline__ void mma16816(float c[4], const u32* a, u32 b0, u32 b1) {
    asm("mma.sync.aligned.m16n8k16.row.col.f32.bf16.bf16.f32 "
        "{%0,%1,%2,%3}, {%4,%5,%6,%7}, {%8,%9}, {%0,%1,%2,%3};"
        : "+f"(c[0]), "+f"(c[1]), "+f"(c[2]), "+f"(c[3])
        : "r"(a[0]), "r"(a[1]), "r"(a[2]), "r"(a[3]), "r"(b0), "r"(b1));
}

#define SHFL(v, L) __shfl_sync(0xffffffffu, (v), (L))

// MMA for one n8 chunk: 3 bf16-split passes (AhBh, AhBl, AlBh), K=64.
#define MMA_CHUNK(ch, A0, B0) do { \
    const u32 _rbHI = BHI + (u32)(((ch) * 8 + qr) * 136 + 4 * j); \
    const u32 _rbLO = BLO + (u32)(((ch) * 8 + qr) * 132 + 4 * j); \
    _Pragma("unroll") \
    for (int _pass = 0; _pass < 3; _pass++) { \
        const u32* _af = (_pass == 2) ? al : ah; \
        const u32 _rb = (_pass == 1) ? _rbLO : _rbHI; \
        _Pragma("unroll") \
        for (int _kt = 0; _kt < 4; _kt++) { \
            u32 _b0 = lds32(_rb + _kt * 32); \
            u32 _b1 = lds32(_rb + _kt * 32 + 16); \
            mma16816(A0, _af + _kt * 4, _b0, _b1); \
            mma16816(B0, _af + 16 + _kt * 4, _b0, _b1); \
        } \
    } \
} while (0)

// ---------------------------------------------------------------------------
// Kernel 1: per-node q pre-contraction (+ zero Z and out)
// ---------------------------------------------------------------------------
__global__ void q_kernel(const float* __restrict__ x,
                         const float* __restrict__ Wq0, const float* __restrict__ Wq1,
                         const float* __restrict__ Wd0, const float* __restrict__ Wd1,
                         float* __restrict__ out)
{
    int n = blockIdx.x * blockDim.x + threadIdx.x;
    if (n >= N_NODES) return;
    g_Z[n] = 0.f;
    float* o = out + (size_t)n * 20;
#pragma unroll
    for (int k = 0; k < 20; k++) o[k] = 0.f;

    const float* xr = x + (size_t)n * 40;
    float q0[8];
#pragma unroll
    for (int b = 0; b < 8; b++) {
        float acc = 0.f;
#pragma unroll
        for (int a = 0; a < 16; a++) acc = fmaf(xr[a], __ldg(Wq0 + a * 8 + b), acc);
        q0[b] = acc;
    }
    float q1[12];
#pragma unroll
    for (int b = 0; b < 4; b++)
#pragma unroll
        for (int c = 0; c < 3; c++) {
            float acc = 0.f;
#pragma unroll
            for (int a = 0; a < 8; a++) acc = fmaf(xr[16 + a * 3 + c], __ldg(Wq1 + a * 4 + b), acc);
            q1[b * 3 + c] = acc;
        }
    float* qo = g_q + (size_t)n * 20;
#pragma unroll
    for (int b = 0; b < 8; b++) {
        float acc = 0.f;
#pragma unroll
        for (int a = 0; a < 8; a++) acc = fmaf(q0[a], __ldg(Wd0 + a * 8 + b), acc);
        qo[b] = acc * S0;
    }
#pragma unroll
    for (int b = 0; b < 4; b++)
#pragma unroll
        for (int c = 0; c < 3; c++) {
            float acc = 0.f;
#pragma unroll
            for (int a = 0; a < 4; a++) acc = fmaf(q1[a * 3 + c], __ldg(Wd1 + a * 4 + b), acc);
            qo[8 + b * 3 + c] = acc * S1;
        }
}

// ---------------------------------------------------------------------------
// Kernel 2: phase-specialized mma.sync edge kernel (256 threads)
//   warps 0-3: K phase (logits), warps 4-7: V phase — fully parallel
// ---------------------------------------------------------------------------
__global__ __launch_bounds__(256, 1)
void edge_kernel(const float* __restrict__ x, const int* __restrict__ ei,
                 const float* __restrict__ eattr, const float* __restrict__ emb,
                 const float* __restrict__ elen,
                 const float* __restrict__ Wk1, const float* __restrict__ Wk2,
                 const float* __restrict__ Wv1, const float* __restrict__ Wv2)
{
    extern __shared__ char smem[];
    const u32 sb = smem_u32(smem);
    const int tid = threadIdx.x;
    const int group = tid >> 7;          // 0 = K phase, 1 = V phase
    const int gt = tid & 127;            // group-local thread / edge row
    const int lane = tid & 31;
    const int j = lane & 3;
    const int qr = lane >> 2;
    const int jh = j >> 1;
    const int wbase = (gt >> 5) << 5;

    // ---- stage W1 (transposed, *0.25, fp32) ----
    float* w1k = (float*)(smem + OFF_W1K);
    float* w1v = (float*)(smem + OFF_W1V);
    for (int idx = tid; idx < 1024; idx += 256) {
        int hh = idx >> 4, a = idx & 15;
        w1k[idx] = Wk1[a * 64 + hh] * 0.25f;
        w1v[idx] = Wv1[a * 64 + hh] * 0.25f;
    }
    // ---- stage W2 (transposed [n][k], *0.125, bf16 hi/lo) ----
    for (int idx = tid; idx < 64 * 288; idx += 256) {
        int k = idx / 288, n = idx % 288;
        u32 offHI = (u32)(n * 136 + k * 2);
        u32 offLO = (u32)(n * 132 + k * 2);
        u16 hb, lb;
        bsplit(Wk2[idx] * 0.125f, hb, lb);
        *(u16*)(smem + OFF_KHI + offHI) = hb;
        *(u16*)(smem + OFF_KLO + offLO) = lb;
        bsplit(Wv2[idx] * 0.125f, hb, lb);
        *(u16*)(smem + OFF_VHI + offHI) = hb;
        *(u16*)(smem + OFF_VLO + offLO) = lb;
    }
    __syncthreads();

    const u32 HHI = sb + (group ? OFF_H1H : OFF_H0H);
    const u32 HLO = sb + (group ? OFF_H1L : OFF_H0L);
    const u32 BHI = sb + (group ? OFF_VHI : OFF_KHI);
    const u32 BLO = sb + (group ? OFF_VLO : OFF_KLO);
    const float* w1 = group ? w1v : w1k;
    const int barid = 1 + group;

    int lanev[4], rowv[4];
#pragma unroll
    for (int rr = 0; rr < 4; rr++) {
        lanev[rr] = (rr >> 1) * 16 + (rr & 1) * 8 + qr;
        rowv[rr] = wbase + lanev[rr];
    }

    for (int tile = blockIdx.x; tile < NTILES; tile += gridDim.x) {
        const int tbase = tile * 128;
        const int e = tbase + gt;

        // ---- own-edge data + ops (registers; shared via shfl in epilogue) ----
        const int dst = ei[E_EDGES + e];
        float y1a, y1b, y1c, el;
        float op_ss[16], op_uu[8], op_su[16], op_us[24];
        ull em2[8];
        {
            const int src = ei[e];
            const float4 ea = *(const float4*)(eattr + (size_t)e * 4);
            const float y0 = ea.x;
            y1a = ea.y; y1b = ea.z; y1c = ea.w;
            el = elen[e];
            const float* xr = x + (size_t)src * 40;
            float xs_[16], xu_[24];
#pragma unroll
            for (int a = 0; a < 16; a++) xs_[a] = __ldg(xr + a);
#pragma unroll
            for (int a = 0; a < 24; a++) xu_[a] = __ldg(xr + 16 + a);
#pragma unroll
            for (int a = 0; a < 16; a++) { op_ss[a] = xs_[a] * y0 * C_SS; op_su[a] = xs_[a] * C_SU; }
#pragma unroll
            for (int a = 0; a < 8; a++)
                op_uu[a] = (xu_[a * 3] * y1a + xu_[a * 3 + 1] * y1b + xu_[a * 3 + 2] * y1c) * C_UU;
            const float y0q = y0 * C_US;
#pragma unroll
            for (int a = 0; a < 24; a++) op_us[a] = xu_[a] * y0q;

            const float4* ep = (const float4*)(emb + (size_t)e * 16);
#pragma unroll
            for (int k = 0; k < 4; k++) {
                float4 t = __ldg(ep + k);
                em2[2 * k]     = packf2(t.x, t.y);
                em2[2 * k + 1] = packf2(t.z, t.w);
            }
        }

        // ---- first layer: h[64] for own edge -> H smem (bf16 hi/lo) ----
#pragma unroll 1
        for (int g = 0; g < 8; g++) {
            float hv[8];
#pragma unroll
            for (int t = 0; t < 8; t++) hv[t] = silu_f(dot16(w1 + (g * 8 + t) * 16, em2));
            u32 hw[4], lw[4];
#pragma unroll
            for (int t = 0; t < 4; t++) {
                u16 h0, l0, h1, l1;
                bsplit(hv[2 * t], h0, l0);
                bsplit(hv[2 * t + 1], h1, l1);
                hw[t] = ((u32)h1 << 16) | h0;
                lw[t] = ((u32)l1 << 16) | l0;
            }
            const u32 so = (u32)(gt * 132 + g * 16);
#pragma unroll
            for (int t = 0; t < 4; t++) {
                sts32(HHI + so + t * 4, hw[t]);
                sts32(HLO + so + t * 4, lw[t]);
            }
        }
        asm volatile("bar.sync %0, 128;" :: "r"(barid) : "memory");

        // ---- A fragments: this warp's 32 rows, K=64, hi+lo ----
        u32 ah[32], al[32];
#pragma unroll
        for (int mt = 0; mt < 2; mt++)
#pragma unroll
            for (int kt = 0; kt < 4; kt++) {
                const u32 rb = (u32)((wbase + mt * 16 + qr) * 132 + 4 * j + kt * 32);
                const int ix = mt * 16 + kt * 4;
                ah[ix + 0] = lds32(HHI + rb);
                ah[ix + 1] = lds32(HHI + rb + 8 * 132);
                ah[ix + 2] = lds32(HHI + rb + 16);
                ah[ix + 3] = lds32(HHI + rb + 8 * 132 + 16);
                al[ix + 0] = lds32(HLO + rb);
                al[ix + 1] = lds32(HLO + rb + 8 * 132);
                al[ix + 2] = lds32(HLO + rb + 16);
                al[ix + 3] = lds32(HLO + rb + 8 * 132 + 16);
            }
        asm volatile("bar.sync %0, 128;" :: "r"(barid) : "memory");   // H reusable

        float p0[4][2]  = {{0,0},{0,0},{0,0},{0,0}};
        float psu[4][2] = {{0,0},{0,0},{0,0},{0,0}};
        float pus[4][6] = {{0,0,0,0,0,0},{0,0,0,0,0,0},{0,0,0,0,0,0},{0,0,0,0,0,0}};

        // ---- ss region: chunks 0..15 ----
#pragma unroll
        for (int ch = 0; ch < 16; ch++) {
            float A0[4] = {0,0,0,0}, B0[4] = {0,0,0,0};
            MMA_CHUNK(ch, A0, B0);
#pragma unroll
            for (int rr = 0; rr < 4; rr++) {
                float o = SHFL(op_ss[ch], lanev[rr]);
                float c0 = (rr < 2) ? A0[(rr & 1) * 2]     : B0[(rr & 1) * 2];
                float c1 = (rr < 2) ? A0[(rr & 1) * 2 + 1] : B0[(rr & 1) * 2 + 1];
                p0[rr][0] = fmaf(c0, o, p0[rr][0]);
                p0[rr][1] = fmaf(c1, o, p0[rr][1]);
            }
        }
        // ---- uu region: chunks 16..23 ----
#pragma unroll
        for (int ch = 16; ch < 24; ch++) {
            float A0[4] = {0,0,0,0}, B0[4] = {0,0,0,0};
            MMA_CHUNK(ch, A0, B0);
#pragma unroll
            for (int rr = 0; rr < 4; rr++) {
                float o = SHFL(op_uu[ch - 16], lanev[rr]);
                float c0 = (rr < 2) ? A0[(rr & 1) * 2]     : B0[(rr & 1) * 2];
                float c1 = (rr < 2) ? A0[(rr & 1) * 2 + 1] : B0[(rr & 1) * 2 + 1];
                p0[rr][0] = fmaf(c0, o, p0[rr][0]);
                p0[rr][1] = fmaf(c1, o, p0[rr][1]);
            }
        }
        // ---- su region: chunks 24..31 (a = 2*(ch-24) + jh) ----
#pragma unroll
        for (int ch = 24; ch < 32; ch++) {
            float A0[4] = {0,0,0,0}, B0[4] = {0,0,0,0};
            MMA_CHUNK(ch, A0, B0);
#pragma unroll
            for (int rr = 0; rr < 4; rr++) {
                float oa = SHFL(op_su[2 * (ch - 24)],     lanev[rr]);
                float ob = SHFL(op_su[2 * (ch - 24) + 1], lanev[rr]);
                float o = jh ? ob : oa;
                float c0 = (rr < 2) ? A0[(rr & 1) * 2]     : B0[(rr & 1) * 2];
                float c1 = (rr < 2) ? A0[(rr & 1) * 2 + 1] : B0[(rr & 1) * 2 + 1];
                psu[rr][0] = fmaf(c0, o, psu[rr][0]);
                psu[rr][1] = fmaf(c1, o, psu[rr][1]);
            }
        }
        // ---- us region: chunks 32..35 (a = 2*(ch-32) + jh) ----
#pragma unroll
        for (int ch = 32; ch < 36; ch++) {
            float A0[4] = {0,0,0,0}, B0[4] = {0,0,0,0};
            MMA_CHUNK(ch, A0, B0);
#pragma unroll
            for (int rr = 0; rr < 4; rr++) {
                float o0a = SHFL(op_us[6 * (ch - 32) + 0], lanev[rr]);
                float o1a = SHFL(op_us[6 * (ch - 32) + 1], lanev[rr]);
                float o2a = SHFL(op_us[6 * (ch - 32) + 2], lanev[rr]);
                float o0b = SHFL(op_us[6 * (ch - 32) + 3], lanev[rr]);
                float o1b = SHFL(op_us[6 * (ch - 32) + 4], lanev[rr]);
                float o2b = SHFL(op_us[6 * (ch - 32) + 5], lanev[rr]);
                float o0 = jh ? o0b : o0a;
                float o1 = jh ? o1b : o1a;
                float o2 = jh ? o2b : o2a;
                float c0 = (rr < 2) ? A0[(rr & 1) * 2]     : B0[(rr & 1) * 2];
                float c1 = (rr < 2) ? A0[(rr & 1) * 2 + 1] : B0[(rr & 1) * 2 + 1];
                pus[rr][0] = fmaf(c0, o0, pus[rr][0]);
                pus[rr][1] = fmaf(c0, o1, pus[rr][1]);
                pus[rr][2] = fmaf(c0, o2, pus[rr][2]);
                pus[rr][3] = fmaf(c1, o0, pus[rr][3]);
                pus[rr][4] = fmaf(c1, o1, pus[rr][4]);
                pus[rr][5] = fmaf(c1, o2, pus[rr][5]);
            }
        }

        if (group == 0) {
            // ---- logit finalize ----
#pragma unroll
            for (int rr = 0; rr < 4; rr++) {
                const int L = lanev[rr];
                const int edge = tbase + rowv[rr];
                const int dstr = SHFL(dst, L);
                const float ya = SHFL(y1a, L), yb = SHFL(y1b, L), yc = SHFL(y1c, L);
                const float elr = SHFL(el, L);
                const float* qd = g_q + (size_t)dstr * 20;
                const int b0 = (2 * j) & 3, b1 = (2 * j + 1) & 3;
                const float qa0 = __ldg(qd + 8 + 3 * b0), qa1 = __ldg(qd + 8 + 3 * b0 + 1), qa2 = __ldg(qd + 8 + 3 * b0 + 2);
                const float qb0 = __ldg(qd + 8 + 3 * b1), qb1 = __ldg(qd + 8 + 3 * b1 + 1), qb2 = __ldg(qd + 8 + 3 * b1 + 2);
                float dp = p0[rr][0] * __ldg(qd + 2 * j) + p0[rr][1] * __ldg(qd + 2 * j + 1);
                dp += psu[rr][0] * (ya * qa0 + yb * qa1 + yc * qa2);
                dp += psu[rr][1] * (ya * qb0 + yb * qb1 + yc * qb2);
                dp += pus[rr][0] * qa0 + pus[rr][1] * qa1 + pus[rr][2] * qa2;
                dp += pus[rr][3] * qb0 + pus[rr][4] * qb1 + pus[rr][5] * qb2;
                dp += __shfl_xor_sync(0xffffffffu, dp, 1);
                dp += __shfl_xor_sync(0xffffffffu, dp, 2);
                if (j == 0) {
                    const float t = 10.f * (1.f - elr * (1.f / 3.15f));
                    const float cut = (t > 0.f) ? expf(-1.f / fmaxf(t, 1e-6f)) : 0.f;
                    const float eat = cut * expf(dp);
                    g_e[edge] = eat;
                    atomicAdd(&g_Z[dstr], eat);
                }
            }
        } else {
            // ---- value finalize ----
#pragma unroll
            for (int rr = 0; rr < 4; rr++) {
                const int L = lanev[rr];
                const int edge = tbase + rowv[rr];
                const float ya = SHFL(y1a, L), yb = SHFL(y1b, L), yc = SHFL(y1c, L);
                float* vp = g_v + (size_t)edge * 20;
                vp[2 * j]     = p0[rr][0];
                vp[2 * j + 1] = p0[rr][1];
                const float s0v = psu[rr][0] + __shfl_xor_sync(0xffffffffu, psu[rr][0], 2);
                const float s1v = psu[rr][1] + __shfl_xor_sync(0xffffffffu, psu[rr][1], 2);
                float ux[6];
#pragma unroll
                for (int c = 0; c < 6; c++)
                    ux[c] = pus[rr][c] + __shfl_xor_sync(0xffffffffu, pus[rr][c], 2);
                if (j < 2) {
                    const int b0 = 2 * j, b1 = 2 * j + 1;
                    vp[8 + 3 * b0]     = fmaf(s0v, ya, ux[0]);
                    vp[8 + 3 * b0 + 1] = fmaf(s0v, yb, ux[1]);
                    vp[8 + 3 * b0 + 2] = fmaf(s0v, yc, ux[2]);
                    vp[8 + 3 * b1]     = fmaf(s1v, ya, ux[3]);
                    vp[8 + 3 * b1 + 1] = fmaf(s1v, yb, ux[4]);
                    vp[8 + 3 * b1 + 2] = fmaf(s1v, yc, ux[5]);
                }
            }
        }
    }
}

// ---------------------------------------------------------------------------
// Kernel 3: normalize + scatter
// ---------------------------------------------------------------------------
__global__ void scatter_kernel(const int* __restrict__ ei, float* __restrict__ out)
{
    int e = blockIdx.x * blockDim.x + threadIdx.x;
    if (e >= E_EDGES) return;
    int dst = ei[E_EDGES + e];
    float w = sqrtf(fmaxf(g_e[e] / g_Z[dst], 0.f));
    const float* vp = g_v + (size_t)e * 20;
    float* op = out + (size_t)dst * 20;
#pragma unroll
    for (int k = 0; k < 20; k++) atomicAdd(op + k, w * __ldg(vp + k));
}

// ---------------------------------------------------------------------------
extern "C" void kernel_launch(void* const* d_in, const int* in_sizes, int n_in,
                              void* d_out, int out_size)
{
    const float* x    = (const float*)d_in[0];
    const int*   ei   = (const int*)d_in[1];
    const float* eatt = (const float*)d_in[2];
    const float* emb  = (const float*)d_in[3];
    const float* elen = (const float*)d_in[4];
    const float* Wq0  = (const float*)d_in[5];
    const float* Wq1  = (const float*)d_in[6];
    const float* Wk1  = (const float*)d_in[7];
    const float* Wk2  = (const float*)d_in[8];
    const float* Wv1  = (const float*)d_in[9];
    const float* Wv2  = (const float*)d_in[10];
    const float* Wd0  = (const float*)d_in[11];
    const float* Wd1  = (const float*)d_in[12];
    float* out = (float*)d_out;

    cudaFuncSetAttribute(edge_kernel, cudaFuncAttributeMaxDynamicSharedMemorySize, SMEM_BYTES);
    int dev = 0, nsm = 148;
    cudaGetDevice(&dev);
    cudaDeviceGetAttribute(&nsm, cudaDevAttrMultiProcessorCount, dev);

    q_kernel<<<(N_NODES + 255) / 256, 256>>>(x, Wq0, Wq1, Wd0, Wd1, out);
    edge_kernel<<<nsm, 256, SMEM_BYTES>>>(x, ei, eatt, emb, elen, Wk1, Wk2, Wv1, Wv2);
    scatter_kernel<<<(E_EDGES + 255) / 256, 256>>>(ei, out);
    (void)in_sizes; (void)n_in; (void)out_size;
}

// round 7
// speedup vs baseline: 2.8180x; 1.4355x over previous
#include <cuda_runtime.h>
#include <cuda_fp16.h>

#define N_NODES 30000
#define E_EDGES 480000
#define NTILES  3750            // E / 128

// ---------------- device scratch (no allocation allowed) ----------------
__device__ float g_e[E_EDGES];
__device__ float g_v[E_EDGES * 20];
__device__ float g_q[N_NODES * 20];
__device__ float g_Z[N_NODES];

#define C_SS 0.17677669529663687f   // 1/(4*sqrt2)
#define C_UU 0.14433756729740643f   // 1/sqrt(48)
#define C_SU 0.17677669529663687f
#define C_US 0.25f                  // 1/(sqrt8*sqrt2)
#define S0   0.022097086912079608f
#define S1   0.036084391824351615f

typedef unsigned long long ull;
typedef unsigned int u32;
typedef unsigned short u16;

// ---------------- SMEM layout (bytes) ----------------
// W2 buffers: 288 rows x 144B, k-pair-permuted (word s holds pair (s/8)+4*(s%8))
// W1 buffers: 64 rows x 32B (natural k order)
// EM buffers: 128 rows x 32B per group, fp16 hi/lo
#define OFF_KHI  0
#define OFF_KLO  41472
#define OFF_VHI  82944
#define OFF_VLO  124416
#define OFF_W1KH 165888
#define OFF_W1KL 167936
#define OFF_W1VH 169984
#define OFF_W1VL 172032
#define OFF_EM0H 174080
#define OFF_EM0L 178176
#define OFF_EM1H 182272
#define OFF_EM1L 186368
#define SMEM_BYTES 190464

// ---------------- helpers ----------------
__device__ __forceinline__ u32 smem_u32(const void* p) {
    u32 a; asm("{ .reg .u64 t; cvta.to.shared.u64 t, %1; cvt.u32.u64 %0, t; }" : "=r"(a) : "l"(p));
    return a;
}
__device__ __forceinline__ u32 lds32(u32 a) {
    u32 v; asm volatile("ld.shared.b32 %0, [%1];" : "=r"(v) : "r"(a)); return v;
}
__device__ __forceinline__ void lds128(u32* r, u32 a) {
    asm volatile("ld.shared.v4.b32 {%0,%1,%2,%3}, [%4];"
                 : "=r"(r[0]), "=r"(r[1]), "=r"(r[2]), "=r"(r[3]) : "r"(a));
}
__device__ __forceinline__ void sts128(u32 a, u32 v0, u32 v1, u32 v2, u32 v3) {
    asm volatile("st.shared.v4.b32 [%0], {%1,%2,%3,%4};" :: "r"(a), "r"(v0), "r"(v1), "r"(v2), "r"(v3) : "memory");
}
__device__ __forceinline__ float silu_f(float x) { return x / (1.f + __expf(-x)); }

__device__ __forceinline__ u32 h2pack(float lo, float hi) {
    __half2 h = __floats2half2_rn(lo, hi);          // .x = lo half
    return *reinterpret_cast<u32*>(&h);
}
__device__ __forceinline__ void hsplit(float x, u16 &h, u16 &l) {
    __half hh = __float2half_rn(x);
    h = __half_as_ushort(hh);
    l = __half_as_ushort(__float2half_rn(x - __half2float(hh)));
}

__device__ __forceinline__ void mma16816(float c[4], const u32* a, u32 b0, u32 b1) {
    asm("mma.sync.aligned.m16n8k16.row.col.f32.f16.f16.f32 "
        "{%0,%1,%2,%3}, {%4,%5,%6,%7}, {%8,%9}, {%0,%1,%2,%3};"
        : "+f"(c[0]), "+f"(c[1]), "+f"(c[2]), "+f"(c[3])
        : "r"(a[0]), "r"(a[1]), "r"(a[2]), "r"(a[3]), "r"(b0), "r"(b1));
}

#define SHFL(v, L) __shfl_sync(0xffffffffu, (v), (L))

// layer-2 chunk: fp16 2-pass (Ah*Bh + Ah*Bl), K=64, permuted v4 B loads
#define MMA_CHUNK(ch, C0, C1) do { \
    const u32 _rb = (u32)(((ch) * 8 + qr) * 144 + 32 * j); \
    u32 _rh[8], _rl[8]; \
    lds128(_rh,     BHI + _rb); lds128(_rh + 4, BHI + _rb + 16); \
    lds128(_rl,     BLO + _rb); lds128(_rl + 4, BLO + _rb + 16); \
    _Pragma("unroll") \
    for (int _kt = 0; _kt < 4; _kt++) { \
        mma16816(C0, ah + _kt * 4,      _rh[2 * _kt], _rh[2 * _kt + 1]); \
        mma16816(C1, ah + 16 + _kt * 4, _rh[2 * _kt], _rh[2 * _kt + 1]); \
        mma16816(C0, ah + _kt * 4,      _rl[2 * _kt], _rl[2 * _kt + 1]); \
        mma16816(C1, ah + 16 + _kt * 4, _rl[2 * _kt], _rl[2 * _kt + 1]); \
    } \
} while (0)

// ---------------------------------------------------------------------------
// Kernel 1: per-node q pre-contraction (+ zero Z and out)
// ---------------------------------------------------------------------------
__global__ void q_kernel(const float* __restrict__ x,
                         const float* __restrict__ Wq0, const float* __restrict__ Wq1,
                         const float* __restrict__ Wd0, const float* __restrict__ Wd1,
                         float* __restrict__ out)
{
    int n = blockIdx.x * blockDim.x + threadIdx.x;
    if (n >= N_NODES) return;
    g_Z[n] = 0.f;
    float* o = out + (size_t)n * 20;
#pragma unroll
    for (int k = 0; k < 20; k++) o[k] = 0.f;

    const float* xr = x + (size_t)n * 40;
    float q0[8];
#pragma unroll
    for (int b = 0; b < 8; b++) {
        float acc = 0.f;
#pragma unroll
        for (int a = 0; a < 16; a++) acc = fmaf(xr[a], __ldg(Wq0 + a * 8 + b), acc);
        q0[b] = acc;
    }
    float q1[12];
#pragma unroll
    for (int b = 0; b < 4; b++)
#pragma unroll
        for (int c = 0; c < 3; c++) {
            float acc = 0.f;
#pragma unroll
            for (int a = 0; a < 8; a++) acc = fmaf(xr[16 + a * 3 + c], __ldg(Wq1 + a * 4 + b), acc);
            q1[b * 3 + c] = acc;
        }
    float* qo = g_q + (size_t)n * 20;
#pragma unroll
    for (int b = 0; b < 8; b++) {
        float acc = 0.f;
#pragma unroll
        for (int a = 0; a < 8; a++) acc = fmaf(q0[a], __ldg(Wd0 + a * 8 + b), acc);
        qo[b] = acc * S0;
    }
#pragma unroll
    for (int b = 0; b < 4; b++)
#pragma unroll
        for (int c = 0; c < 3; c++) {
            float acc = 0.f;
#pragma unroll
            for (int a = 0; a < 4; a++) acc = fmaf(q1[a * 3 + c], __ldg(Wd1 + a * 4 + b), acc);
            qo[8 + b * 3 + c] = acc * S1;
        }
}

// ---------------------------------------------------------------------------
// Kernel 2: all-tensor-core edge kernel, zero per-tile barriers
// ---------------------------------------------------------------------------
__global__ __launch_bounds__(256, 1)
void edge_kernel(const float* __restrict__ x, const int* __restrict__ ei,
                 const float* __restrict__ eattr, const float* __restrict__ emb,
                 const float* __restrict__ elen,
                 const float* __restrict__ Wk1, const float* __restrict__ Wk2,
                 const float* __restrict__ Wv1, const float* __restrict__ Wv2)
{
    extern __shared__ char smem[];
    const u32 sb = smem_u32(smem);
    const int tid = threadIdx.x;
    const int group = tid >> 7;          // 0 = K phase, 1 = V phase
    const int gt = tid & 127;            // group-local thread / edge row
    const int lane = tid & 31;
    const int j = lane & 3;
    const int qr = lane >> 2;
    const int jh = j >> 1;
    const int wbase = (gt >> 5) << 5;

    // ---- stage W1 (fp16 hi/lo, [h-row][k=a], *0.25) ----
    for (int idx = tid; idx < 1024; idx += 256) {
        int a = idx >> 6, h = idx & 63;
        u32 off = (u32)(h * 32 + a * 2);
        u16 hb, lb;
        hsplit(Wk1[idx] * 0.25f, hb, lb);
        *(u16*)(smem + OFF_W1KH + off) = hb;
        *(u16*)(smem + OFF_W1KL + off) = lb;
        hsplit(Wv1[idx] * 0.25f, hb, lb);
        *(u16*)(smem + OFF_W1VH + off) = hb;
        *(u16*)(smem + OFF_W1VL + off) = lb;
    }
    // ---- stage W2 (fp16 hi/lo, [n-row][k permuted], *0.125) ----
    for (int idx = tid; idx < 64 * 288; idx += 256) {
        int k = idx / 288, n = idx % 288;
        int p = k >> 1;
        int s = (p & 3) * 8 + (p >> 2);                 // k-pair permutation
        u32 off = (u32)(n * 144 + s * 4 + (k & 1) * 2);
        u16 hb, lb;
        hsplit(Wk2[idx] * 0.125f, hb, lb);
        *(u16*)(smem + OFF_KHI + off) = hb;
        *(u16*)(smem + OFF_KLO + off) = lb;
        hsplit(Wv2[idx] * 0.125f, hb, lb);
        *(u16*)(smem + OFF_VHI + off) = hb;
        *(u16*)(smem + OFF_VLO + off) = lb;
    }
    __syncthreads();

    const u32 BHI = sb + (group ? OFF_VHI : OFF_KHI);
    const u32 BLO = sb + (group ? OFF_VLO : OFF_KLO);
    const u32 W1H = sb + (group ? OFF_W1VH : OFF_W1KH);
    const u32 W1L = sb + (group ? OFF_W1VL : OFF_W1KL);
    const u32 EMH = sb + (group ? OFF_EM1H : OFF_EM0H);
    const u32 EML = sb + (group ? OFF_EM1L : OFF_EM0L);

    int lanev[4], rowv[4];
#pragma unroll
    for (int rr = 0; rr < 4; rr++) {
        lanev[rr] = (rr >> 1) * 16 + (rr & 1) * 8 + qr;
        rowv[rr] = wbase + lanev[rr];
    }

    for (int tile = blockIdx.x; tile < NTILES; tile += gridDim.x) {
        const int tbase = tile * 128;
        const int e = tbase + gt;

        // ---- own-edge data + ops (registers; shared via shfl in epilogue) ----
        const int dst = ei[E_EDGES + e];
        float y1a, y1b, y1c, el;
        float op_ss[16], op_uu[8], op_su[16], op_us[24];
        {
            const int src = ei[e];
            const float4 ea = *(const float4*)(eattr + (size_t)e * 4);
            const float y0 = ea.x;
            y1a = ea.y; y1b = ea.z; y1c = ea.w;
            el = elen[e];
            const float* xr = x + (size_t)src * 40;
            float xs_[16], xu_[24];
#pragma unroll
            for (int a = 0; a < 16; a++) xs_[a] = __ldg(xr + a);
#pragma unroll
            for (int a = 0; a < 24; a++) xu_[a] = __ldg(xr + 16 + a);
#pragma unroll
            for (int a = 0; a < 16; a++) { op_ss[a] = xs_[a] * y0 * C_SS; op_su[a] = xs_[a] * C_SU; }
#pragma unroll
            for (int a = 0; a < 8; a++)
                op_uu[a] = (xu_[a * 3] * y1a + xu_[a * 3 + 1] * y1b + xu_[a * 3 + 2] * y1c) * C_UU;
            const float y0q = y0 * C_US;
#pragma unroll
            for (int a = 0; a < 24; a++) op_us[a] = xu_[a] * y0q;
        }

        // ---- EM (own edge row) -> SMEM as fp16 hi/lo, warp-local exchange ----
        {
            const float4* ep = (const float4*)(emb + (size_t)e * 16);
            float em_[16];
#pragma unroll
            for (int k = 0; k < 4; k++) {
                float4 t = __ldg(ep + k);
                em_[4 * k] = t.x; em_[4 * k + 1] = t.y; em_[4 * k + 2] = t.z; em_[4 * k + 3] = t.w;
            }
            u32 hw[8], lw[8];
#pragma unroll
            for (int w = 0; w < 8; w++) {
                u16 h0, l0, h1, l1;
                hsplit(em_[2 * w], h0, l0);
                hsplit(em_[2 * w + 1], h1, l1);
                hw[w] = ((u32)h1 << 16) | h0;
                lw[w] = ((u32)l1 << 16) | l0;
            }
            const u32 rb = (u32)(gt * 32);
            sts128(EMH + rb,      hw[0], hw[1], hw[2], hw[3]);
            sts128(EMH + rb + 16, hw[4], hw[5], hw[6], hw[7]);
            sts128(EML + rb,      lw[0], lw[1], lw[2], lw[3]);
            sts128(EML + rb + 16, lw[4], lw[5], lw[6], lw[7]);
        }
        __syncwarp();

        // ---- EM a-frags (rows within own warp) ----
        u32 ehm[2][4], elm[2][4];
#pragma unroll
        for (int mt = 0; mt < 2; mt++) {
            const u32 R0 = (u32)((wbase + 16 * mt + qr) * 32);
            const u32 R1 = R0 + 8 * 32;
            ehm[mt][0] = lds32(EMH + R0 + 4 * j);
            ehm[mt][1] = lds32(EMH + R1 + 4 * j);
            ehm[mt][2] = lds32(EMH + R0 + 16 + 4 * j);
            ehm[mt][3] = lds32(EMH + R1 + 16 + 4 * j);
            elm[mt][0] = lds32(EML + R0 + 4 * j);
            elm[mt][1] = lds32(EML + R1 + 4 * j);
            elm[mt][2] = lds32(EML + R0 + 16 + 4 * j);
            elm[mt][3] = lds32(EML + R1 + 16 + 4 * j);
        }
        __syncwarp();   // EM buffer reusable next tile

        // ---- layer-1 via mma (K=16, 3-pass), c-frags become layer-2 a-frags ----
        u32 ah[32];
#pragma unroll
        for (int ktp = 0; ktp < 4; ktp++) {
            float cA0[4] = {0,0,0,0}, cA1[4] = {0,0,0,0};
            float cB0[4] = {0,0,0,0}, cB1[4] = {0,0,0,0};
            const u32 rA = (u32)(((2 * ktp) * 8 + qr) * 32 + 4 * j);
            const u32 rB = rA + 256;
            const u32 bh0A = lds32(W1H + rA), bh1A = lds32(W1H + rA + 16);
            const u32 bl0A = lds32(W1L + rA), bl1A = lds32(W1L + rA + 16);
            const u32 bh0B = lds32(W1H + rB), bh1B = lds32(W1H + rB + 16);
            const u32 bl0B = lds32(W1L + rB), bl1B = lds32(W1L + rB + 16);
            mma16816(cA0, ehm[0], bh0A, bh1A); mma16816(cA1, ehm[1], bh0A, bh1A);
            mma16816(cB0, ehm[0], bh0B, bh1B); mma16816(cB1, ehm[1], bh0B, bh1B);
            mma16816(cA0, ehm[0], bl0A, bl1A); mma16816(cA1, ehm[1], bl0A, bl1A);
            mma16816(cB0, ehm[0], bl0B, bl1B); mma16816(cB1, ehm[1], bl0B, bl1B);
            mma16816(cA0, elm[0], bh0A, bh1A); mma16816(cA1, elm[1], bh0A, bh1A);
            mma16816(cB0, elm[0], bh0B, bh1B); mma16816(cB1, elm[1], bh0B, bh1B);
            ah[ktp * 4 + 0]      = h2pack(silu_f(cA0[0]), silu_f(cA0[1]));
            ah[ktp * 4 + 1]      = h2pack(silu_f(cA0[2]), silu_f(cA0[3]));
            ah[ktp * 4 + 2]      = h2pack(silu_f(cB0[0]), silu_f(cB0[1]));
            ah[ktp * 4 + 3]      = h2pack(silu_f(cB0[2]), silu_f(cB0[3]));
            ah[16 + ktp * 4 + 0] = h2pack(silu_f(cA1[0]), silu_f(cA1[1]));
            ah[16 + ktp * 4 + 1] = h2pack(silu_f(cA1[2]), silu_f(cA1[3]));
            ah[16 + ktp * 4 + 2] = h2pack(silu_f(cB1[0]), silu_f(cB1[1]));
            ah[16 + ktp * 4 + 3] = h2pack(silu_f(cB1[2]), silu_f(cB1[3]));
        }

        // ---- layer-2: 36 n8 chunks, fp16 2-pass ----
        float p0[4][2]  = {{0,0},{0,0},{0,0},{0,0}};
        float psu[4][2] = {{0,0},{0,0},{0,0},{0,0}};
        float pus[4][6] = {{0,0,0,0,0,0},{0,0,0,0,0,0},{0,0,0,0,0,0},{0,0,0,0,0,0}};

#pragma unroll
        for (int ch = 0; ch < 16; ch++) {          // ss
            float A0[4] = {0,0,0,0}, B0[4] = {0,0,0,0};
            MMA_CHUNK(ch, A0, B0);
#pragma unroll
            for (int rr = 0; rr < 4; rr++) {
                float o = SHFL(op_ss[ch], lanev[rr]);
                float c0 = (rr < 2) ? A0[(rr & 1) * 2]     : B0[(rr & 1) * 2];
                float c1 = (rr < 2) ? A0[(rr & 1) * 2 + 1] : B0[(rr & 1) * 2 + 1];
                p0[rr][0] = fmaf(c0, o, p0[rr][0]);
                p0[rr][1] = fmaf(c1, o, p0[rr][1]);
            }
        }
#pragma unroll
        for (int ch = 16; ch < 24; ch++) {         // uu
            float A0[4] = {0,0,0,0}, B0[4] = {0,0,0,0};
            MMA_CHUNK(ch, A0, B0);
#pragma unroll
            for (int rr = 0; rr < 4; rr++) {
                float o = SHFL(op_uu[ch - 16], lanev[rr]);
                float c0 = (rr < 2) ? A0[(rr & 1) * 2]     : B0[(rr & 1) * 2];
                float c1 = (rr < 2) ? A0[(rr & 1) * 2 + 1] : B0[(rr & 1) * 2 + 1];
                p0[rr][0] = fmaf(c0, o, p0[rr][0]);
                p0[rr][1] = fmaf(c1, o, p0[rr][1]);
            }
        }
#pragma unroll
        for (int ch = 24; ch < 32; ch++) {         // su
            float A0[4] = {0,0,0,0}, B0[4] = {0,0,0,0};
            MMA_CHUNK(ch, A0, B0);
#pragma unroll
            for (int rr = 0; rr < 4; rr++) {
                float oa = SHFL(op_su[2 * (ch - 24)],     lanev[rr]);
                float ob = SHFL(op_su[2 * (ch - 24) + 1], lanev[rr]);
                float o = jh ? ob : oa;
                float c0 = (rr < 2) ? A0[(rr & 1) * 2]     : B0[(rr & 1) * 2];
                float c1 = (rr < 2) ? A0[(rr & 1) * 2 + 1] : B0[(rr & 1) * 2 + 1];
                psu[rr][0] = fmaf(c0, o, psu[rr][0]);
                psu[rr][1] = fmaf(c1, o, psu[rr][1]);
            }
        }
#pragma unroll
        for (int ch = 32; ch < 36; ch++) {         // us
            float A0[4] = {0,0,0,0}, B0[4] = {0,0,0,0};
            MMA_CHUNK(ch, A0, B0);
#pragma unroll
            for (int rr = 0; rr < 4; rr++) {
                float o0a = SHFL(op_us[6 * (ch - 32) + 0], lanev[rr]);
                float o1a = SHFL(op_us[6 * (ch - 32) + 1], lanev[rr]);
                float o2a = SHFL(op_us[6 * (ch - 32) + 2], lanev[rr]);
                float o0b = SHFL(op_us[6 * (ch - 32) + 3], lanev[rr]);
                float o1b = SHFL(op_us[6 * (ch - 32) + 4], lanev[rr]);
                float o2b = SHFL(op_us[6 * (ch - 32) + 5], lanev[rr]);
                float o0 = jh ? o0b : o0a;
                float o1 = jh ? o1b : o1a;
                float o2 = jh ? o2b : o2a;
                float c0 = (rr < 2) ? A0[(rr & 1) * 2]     : B0[(rr & 1) * 2];
                float c1 = (rr < 2) ? A0[(rr & 1) * 2 + 1] : B0[(rr & 1) * 2 + 1];
                pus[rr][0] = fmaf(c0, o0, pus[rr][0]);
                pus[rr][1] = fmaf(c0, o1, pus[rr][1]);
                pus[rr][2] = fmaf(c0, o2, pus[rr][2]);
                pus[rr][3] = fmaf(c1, o0, pus[rr][3]);
                pus[rr][4] = fmaf(c1, o1, pus[rr][4]);
                pus[rr][5] = fmaf(c1, o2, pus[rr][5]);
            }
        }

        if (group == 0) {
            // ---- logit finalize ----
#pragma unroll
            for (int rr = 0; rr < 4; rr++) {
                const int L = lanev[rr];
                const int edge = tbase + rowv[rr];
                const int dstr = SHFL(dst, L);
                const float ya = SHFL(y1a, L), yb = SHFL(y1b, L), yc = SHFL(y1c, L);
                const float elr = SHFL(el, L);
                const float* qd = g_q + (size_t)dstr * 20;
                const int b0 = (2 * j) & 3, b1 = (2 * j + 1) & 3;
                const float qa0 = __ldg(qd + 8 + 3 * b0), qa1 = __ldg(qd + 8 + 3 * b0 + 1), qa2 = __ldg(qd + 8 + 3 * b0 + 2);
                const float qb0 = __ldg(qd + 8 + 3 * b1), qb1 = __ldg(qd + 8 + 3 * b1 + 1), qb2 = __ldg(qd + 8 + 3 * b1 + 2);
                float dp = p0[rr][0] * __ldg(qd + 2 * j) + p0[rr][1] * __ldg(qd + 2 * j + 1);
                dp += psu[rr][0] * (ya * qa0 + yb * qa1 + yc * qa2);
                dp += psu[rr][1] * (ya * qb0 + yb * qb1 + yc * qb2);
                dp += pus[rr][0] * qa0 + pus[rr][1] * qa1 + pus[rr][2] * qa2;
                dp += pus[rr][3] * qb0 + pus[rr][4] * qb1 + pus[rr][5] * qb2;
                dp += __shfl_xor_sync(0xffffffffu, dp, 1);
                dp += __shfl_xor_sync(0xffffffffu, dp, 2);
                if (j == 0) {
                    const float t = 10.f * (1.f - elr * (1.f / 3.15f));
                    const float cut = (t > 0.f) ? expf(-1.f / fmaxf(t, 1e-6f)) : 0.f;
                    const float eat = cut * expf(dp);
                    g_e[edge] = eat;
                    atomicAdd(&g_Z[dstr], eat);
                }
            }
        } else {
            // ---- value finalize ----
#pragma unroll
            for (int rr = 0; rr < 4; rr++) {
                const int L = lanev[rr];
                const int edge = tbase + rowv[rr];
                const float ya = SHFL(y1a, L), yb = SHFL(y1b, L), yc = SHFL(y1c, L);
                float* vp = g_v + (size_t)edge * 20;
                vp[2 * j]     = p0[rr][0];
                vp[2 * j + 1] = p0[rr][1];
                const float s0v = psu[rr][0] + __shfl_xor_sync(0xffffffffu, psu[rr][0], 2);
                const float s1v = psu[rr][1] + __shfl_xor_sync(0xffffffffu, psu[rr][1], 2);
                float ux[6];
#pragma unroll
                for (int c = 0; c < 6; c++)
                    ux[c] = pus[rr][c] + __shfl_xor_sync(0xffffffffu, pus[rr][c], 2);
                if (j < 2) {
                    const int b0 = 2 * j, b1 = 2 * j + 1;
                    vp[8 + 3 * b0]     = fmaf(s0v, ya, ux[0]);
                    vp[8 + 3 * b0 + 1] = fmaf(s0v, yb, ux[1]);
                    vp[8 + 3 * b0 + 2] = fmaf(s0v, yc, ux[2]);
                    vp[8 + 3 * b1]     = fmaf(s1v, ya, ux[3]);
                    vp[8 + 3 * b1 + 1] = fmaf(s1v, yb, ux[4]);
                    vp[8 + 3 * b1 + 2] = fmaf(s1v, yc, ux[5]);
                }
            }
        }
    }
}

// ---------------------------------------------------------------------------
// Kernel 3: normalize + scatter
// ---------------------------------------------------------------------------
__global__ void scatter_kernel(const int* __restrict__ ei, float* __restrict__ out)
{
    int e = blockIdx.x * blockDim.x + threadIdx.x;
    if (e >= E_EDGES) return;
    int dst = ei[E_EDGES + e];
    float w = sqrtf(fmaxf(g_e[e] / g_Z[dst], 0.f));
    const float* vp = g_v + (size_t)e * 20;
    float* op = out + (size_t)dst * 20;
#pragma unroll
    for (int k = 0; k < 20; k++) atomicAdd(op + k, w * __ldg(vp + k));
}

// ---------------------------------------------------------------------------
extern "C" void kernel_launch(void* const* d_in, const int* in_sizes, int n_in,
                              void* d_out, int out_size)
{
    const float* x    = (const float*)d_in[0];
    const int*   ei   = (const int*)d_in[1];
    const float* eatt = (const float*)d_in[2];
    const float* emb  = (const float*)d_in[3];
    const float* elen = (const float*)d_in[4];
    const float* Wq0  = (const float*)d_in[5];
    const float* Wq1  = (const float*)d_in[6];
    const float* Wk1  = (const float*)d_in[7];
    const float* Wk2  = (const float*)d_in[8];
    const float* Wv1  = (const float*)d_in[9];
    const float* Wv2  = (const float*)d_in[10];
    const float* Wd0  = (const float*)d_in[11];
    const float* Wd1  = (const float*)d_in[12];
    float* out = (float*)d_out;

    cudaFuncSetAttribute(edge_kernel, cudaFuncAttributeMaxDynamicSharedMemorySize, SMEM_BYTES);
    int dev = 0, nsm = 148;
    cudaGetDevice(&dev);
    cudaDeviceGetAttribute(&nsm, cudaDevAttrMultiProcessorCount, dev);

    q_kernel<<<(N_NODES + 255) / 256, 256>>>(x, Wq0, Wq1, Wd0, Wd1, out);
    edge_kernel<<<nsm, 256, SMEM_BYTES>>>(x, ei, eatt, emb, elen, Wk1, Wk2, Wv1, Wv2);
    scatter_kernel<<<(E_EDGES + 255) / 256, 256>>>(ei, out);
    (void)in_sizes; (void)n_in; (void)out_size;
}